// round 1
// baseline (speedup 1.0000x reference)
#include <cuda_runtime.h>
#include <math.h>
#include <stdint.h>

// Problem constants (fixed shapes from reference)
#define N_TOK 4096          // B*S = 2*2048
#define HID   1024
#define FF    2816
#define FF2   (2*FF)        // 5632
#define NEXP  8
#define NSLOT (N_TOK*2)     // top-k = 2

// ---------------- scratch (static device globals; no runtime alloc) --------
static __device__ int   g_cnt[NEXP];
static __device__ int   g_off[NEXP+1];
static __device__ int   g_pos[NEXP];
static __device__ int   g_slot_token[NSLOT];   // permuted row -> token id
static __device__ int   g_slot_out[NSLOT];     // permuted row -> t*2 + k
static __device__ float g_slot_score[NSLOT];   // permuted row -> routing score
static __device__ int   g_tok_exp[NSLOT];      // (t,k) -> expert
static __device__ float g_tok_score[NSLOT];    // (t,k) -> score
static __device__ float g_h1  [(size_t)NSLOT * FF2];  // GEMM1 out  (184 MB)
static __device__ float g_act [(size_t)NSLOT * FF ];  // GLU out    ( 92 MB)
static __device__ float g_ybuf[(size_t)NSLOT * HID];  // GEMM2 out  ( 33 MB)

// ---------------- kernel 0: reset counters ---------------------------------
__global__ void init_kernel() {
    if (threadIdx.x < NEXP) g_cnt[threadIdx.x] = 0;
}

// ---------------- kernel 1: router (attention router + top-2) --------------
// One warp per token. mixed = x @ wqkv.T (24 dots of length 1024),
// then tiny 8x8 softmax-attention, top-2, softmax over top-2 logits.
__global__ __launch_bounds__(256) void router_kernel(
    const float* __restrict__ x, const float* __restrict__ wqkv)
{
    const int warp = threadIdx.x >> 5;
    const int lane = threadIdx.x & 31;
    const int t = blockIdx.x * 8 + warp;
    if (t >= N_TOK) return;

    const float* xr = x + (size_t)t * HID;
    float acc[24];
#pragma unroll
    for (int r = 0; r < 24; r++) acc[r] = 0.f;

    for (int j = lane; j < HID; j += 32) {
        const float xv = xr[j];
#pragma unroll
        for (int r = 0; r < 24; r++) acc[r] += xv * wqkv[r * HID + j];
    }
#pragma unroll
    for (int r = 0; r < 24; r++) {
#pragma unroll
        for (int o = 16; o > 0; o >>= 1)
            acc[r] += __shfl_down_sync(0xffffffffu, acc[r], o);
    }

    if (lane == 0) {
        float q[8], k[8], v[8], logit[8];
#pragma unroll
        for (int i = 0; i < 8; i++) { q[i]=acc[i]; k[i]=acc[8+i]; v[i]=acc[16+i]; }
#pragma unroll
        for (int e = 0; e < 8; e++) {
            float m = -1e30f;
#pragma unroll
            for (int j = 0; j < 8; j++) m = fmaxf(m, q[e]*k[j]);
            float s = 0.f, num = 0.f;
#pragma unroll
            for (int j = 0; j < 8; j++) {
                const float w = expf(q[e]*k[j] - m);
                s += w; num += w * v[j];
            }
            logit[e] = num / s;
        }
        // top-2, ties broken by lowest index (matches jax.lax.top_k)
        int i1 = 0;
        for (int e = 1; e < 8; e++) if (logit[e] > logit[i1]) i1 = e;
        int i2 = -1;
        for (int e = 0; e < 8; e++) {
            if (e == i1) continue;
            if (i2 < 0 || logit[e] > logit[i2]) i2 = e;
        }
        const float l1 = logit[i1], l2 = logit[i2];
        const float e2 = expf(l2 - l1);          // l2 <= l1 -> no overflow
        const float s1 = 1.f / (1.f + e2);
        const float s2 = e2 / (1.f + e2);
        g_tok_exp[t*2]     = i1;  g_tok_exp[t*2+1]   = i2;
        g_tok_score[t*2]   = s1;  g_tok_score[t*2+1] = s2;
        atomicAdd(&g_cnt[i1], 1);
        atomicAdd(&g_cnt[i2], 1);
    }
}

// ---------------- kernel 2: exclusive scan over 8 expert counts ------------
__global__ void scan_kernel() {
    int off = 0;
    for (int e = 0; e < NEXP; e++) {
        g_off[e] = off; g_pos[e] = off; off += g_cnt[e];
    }
    g_off[NEXP] = off;   // == NSLOT
}

// ---------------- kernel 3: scatter slots into expert bins -----------------
__global__ void scatter_kernel() {
    const int s = blockIdx.x * blockDim.x + threadIdx.x;
    if (s >= NSLOT) return;
    const int e = g_tok_exp[s];
    const int p = atomicAdd(&g_pos[e], 1);
    g_slot_token[p] = s >> 1;
    g_slot_out[p]   = s;
    g_slot_score[p] = g_tok_score[s];
}

// ---------------- kernel 4: grouped GEMM1  h1 = gather(x) @ w1[e].T --------
// 128x128x8 tile, 256 threads, 8x8 microtile per thread.
__global__ __launch_bounds__(256) void gemm1_kernel(
    const float* __restrict__ x, const float* __restrict__ w1)
{
    const int e     = blockIdx.z;
    const int row0  = g_off[e];
    const int cnt   = g_off[e+1] - row0;
    const int mbase = blockIdx.y * 128;
    if (mbase >= cnt) return;                     // early-exit empty tiles
    const int nbase = blockIdx.x * 128;

    __shared__ float As[8][132];
    __shared__ float Bs[8][132];

    const int tid  = threadIdx.x;
    const int lrow = tid >> 1;                    // 0..127
    const int lk   = (tid & 1) * 4;               // 0 or 4

    int gm = mbase + lrow;
    if (gm > cnt - 1) gm = cnt - 1;               // clamp (row skipped at store)
    const float* Ap = x  + (size_t)g_slot_token[row0 + gm] * HID + lk;
    const float* Bp = w1 + (size_t)e * FF2 * HID
                         + (size_t)(nbase + lrow) * HID + lk;

    const int tx = tid & 15, ty = tid >> 4;
    float acc[8][8];
#pragma unroll
    for (int i = 0; i < 8; i++)
#pragma unroll
        for (int j = 0; j < 8; j++) acc[i][j] = 0.f;

    for (int k0 = 0; k0 < HID; k0 += 8) {
        const float4 av = *(const float4*)(Ap + k0);
        const float4 bv = *(const float4*)(Bp + k0);
        As[lk+0][lrow]=av.x; As[lk+1][lrow]=av.y; As[lk+2][lrow]=av.z; As[lk+3][lrow]=av.w;
        Bs[lk+0][lrow]=bv.x; Bs[lk+1][lrow]=bv.y; Bs[lk+2][lrow]=bv.z; Bs[lk+3][lrow]=bv.w;
        __syncthreads();
#pragma unroll
        for (int kk = 0; kk < 8; kk++) {
            float a[8], b[8];
            *(float4*)(a)   = *(const float4*)(&As[kk][ty*8]);
            *(float4*)(a+4) = *(const float4*)(&As[kk][ty*8+4]);
            *(float4*)(b)   = *(const float4*)(&Bs[kk][tx*8]);
            *(float4*)(b+4) = *(const float4*)(&Bs[kk][tx*8+4]);
#pragma unroll
            for (int i = 0; i < 8; i++)
#pragma unroll
                for (int j = 0; j < 8; j++)
                    acc[i][j] = fmaf(a[i], b[j], acc[i][j]);
        }
        __syncthreads();
    }
#pragma unroll
    for (int i = 0; i < 8; i++) {
        const int m = mbase + ty*8 + i;
        if (m < cnt) {
            float* C = g_h1 + (size_t)(row0 + m) * FF2 + nbase + tx*8;
            *(float4*)(C)   = make_float4(acc[i][0], acc[i][1], acc[i][2], acc[i][3]);
            *(float4*)(C+4) = make_float4(acc[i][4], acc[i][5], acc[i][6], acc[i][7]);
        }
    }
}

// ---------------- kernel 5: GLU  act = silu(a) * g --------------------------
__global__ void glu_kernel() {
    const size_t total = (size_t)NSLOT * (FF/4);
    for (size_t i = (size_t)blockIdx.x * blockDim.x + threadIdx.x;
         i < total; i += (size_t)gridDim.x * blockDim.x) {
        const size_t p  = i / (FF/4);
        const size_t f4 = i % (FF/4);
        const float4 a = *((const float4*)(g_h1 + p*FF2)      + f4);
        const float4 g = *((const float4*)(g_h1 + p*FF2 + FF) + f4);
        float4 o;
        o.x = a.x / (1.f + expf(-a.x)) * g.x;
        o.y = a.y / (1.f + expf(-a.y)) * g.y;
        o.z = a.z / (1.f + expf(-a.z)) * g.z;
        o.w = a.w / (1.f + expf(-a.w)) * g.w;
        *((float4*)(g_act + p*FF) + f4) = o;
    }
}

// ---------------- kernel 6: grouped GEMM2  y = (act @ w2[e].T) * score -----
__global__ __launch_bounds__(256) void gemm2_kernel(
    const float* __restrict__ w2)
{
    const int e     = blockIdx.z;
    const int row0  = g_off[e];
    const int cnt   = g_off[e+1] - row0;
    const int mbase = blockIdx.y * 128;
    if (mbase >= cnt) return;
    const int nbase = blockIdx.x * 128;

    __shared__ float As[8][132];
    __shared__ float Bs[8][132];

    const int tid  = threadIdx.x;
    const int lrow = tid >> 1;
    const int lk   = (tid & 1) * 4;

    int gm = mbase + lrow;
    if (gm > cnt - 1) gm = cnt - 1;
    const float* Ap = g_act + (size_t)(row0 + gm) * FF + lk;
    const float* Bp = w2 + (size_t)e * HID * FF
                         + (size_t)(nbase + lrow) * FF + lk;

    const int tx = tid & 15, ty = tid >> 4;
    float acc[8][8];
#pragma unroll
    for (int i = 0; i < 8; i++)
#pragma unroll
        for (int j = 0; j < 8; j++) acc[i][j] = 0.f;

    for (int k0 = 0; k0 < FF; k0 += 8) {
        const float4 av = *(const float4*)(Ap + k0);
        const float4 bv = *(const float4*)(Bp + k0);
        As[lk+0][lrow]=av.x; As[lk+1][lrow]=av.y; As[lk+2][lrow]=av.z; As[lk+3][lrow]=av.w;
        Bs[lk+0][lrow]=bv.x; Bs[lk+1][lrow]=bv.y; Bs[lk+2][lrow]=bv.z; Bs[lk+3][lrow]=bv.w;
        __syncthreads();
#pragma unroll
        for (int kk = 0; kk < 8; kk++) {
            float a[8], b[8];
            *(float4*)(a)   = *(const float4*)(&As[kk][ty*8]);
            *(float4*)(a+4) = *(const float4*)(&As[kk][ty*8+4]);
            *(float4*)(b)   = *(const float4*)(&Bs[kk][tx*8]);
            *(float4*)(b+4) = *(const float4*)(&Bs[kk][tx*8+4]);
#pragma unroll
            for (int i = 0; i < 8; i++)
#pragma unroll
                for (int j = 0; j < 8; j++)
                    acc[i][j] = fmaf(a[i], b[j], acc[i][j]);
        }
        __syncthreads();
    }
#pragma unroll
    for (int i = 0; i < 8; i++) {
        const int m = mbase + ty*8 + i;
        if (m < cnt) {
            const int   p  = row0 + m;
            const float sc = g_slot_score[p];
            float* C = g_ybuf + (size_t)g_slot_out[p] * HID + nbase + tx*8;
            *(float4*)(C)   = make_float4(sc*acc[i][0], sc*acc[i][1], sc*acc[i][2], sc*acc[i][3]);
            *(float4*)(C+4) = make_float4(sc*acc[i][4], sc*acc[i][5], sc*acc[i][6], sc*acc[i][7]);
        }
    }
}

// ---------------- kernel 7: top-k combine  out[t] = y[2t] + y[2t+1] --------
__global__ void combine_kernel(float* __restrict__ out) {
    const size_t total = (size_t)N_TOK * (HID/4);
    const size_t i = (size_t)blockIdx.x * blockDim.x + threadIdx.x;
    if (i >= total) return;
    const size_t t  = i / (HID/4);
    const size_t j4 = i % (HID/4);
    const float4 y0 = *((const float4*)(g_ybuf + (size_t)(2*t  ) * HID) + j4);
    const float4 y1 = *((const float4*)(g_ybuf + (size_t)(2*t+1) * HID) + j4);
    ((float4*)out)[i] = make_float4(y0.x+y1.x, y0.y+y1.y, y0.z+y1.z, y0.w+y1.w);
}

// ---------------- launch ----------------------------------------------------
extern "C" void kernel_launch(void* const* d_in, const int* in_sizes, int n_in,
                              void* d_out, int out_size)
{
    const float* x    = (const float*)d_in[0];   // (2,2048,1024)
    const float* wqkv = (const float*)d_in[1];   // (24,1024)
    const float* w1   = (const float*)d_in[2];   // (8,5632,1024)
    const float* w2   = (const float*)d_in[3];   // (8,1024,2816)
    float* out = (float*)d_out;                  // (2,2048,1024)

    init_kernel<<<1, 32>>>();
    router_kernel<<<N_TOK/8, 256>>>(x, wqkv);
    scan_kernel<<<1, 1>>>();
    scatter_kernel<<<NSLOT/256, 256>>>();

    gemm1_kernel<<<dim3(FF2/128, NSLOT/128, NEXP), 256>>>(x, w1);
    glu_kernel<<<2048, 256>>>();
    gemm2_kernel<<<dim3(HID/128, NSLOT/128, NEXP), 256>>>(w2);
    combine_kernel<<<(N_TOK*HID/4 + 255)/256, 256>>>(out);
}

// round 6
// speedup vs baseline: 2.7109x; 2.7109x over previous
#include <cuda_runtime.h>
#include <math.h>
#include <stdint.h>

// Problem constants (fixed shapes)
#define N_TOK 4096          // B*S
#define HID   1024
#define FF    2816
#define FF2   5632
#define NEXP  8
#define NSLOT 8192          // N_TOK * top_k

#define ROWW  36            // padded SMEM row (floats): stride 4 banks, 16B-aligned

// ---------------- scratch (static device globals) ---------------------------
static __device__ int   g_cnt[NEXP];
static __device__ int   g_off[NEXP+1];
static __device__ int   g_pos[NEXP];
static __device__ int   g_slot_token[NSLOT];
static __device__ int   g_slot_out[NSLOT];
static __device__ float g_slot_score[NSLOT];
static __device__ int   g_tok_exp[NSLOT];
static __device__ float g_tok_score[NSLOT];
static __device__ float g_act [(size_t)NSLOT * FF ];   // GLU output (92 MB)
static __device__ float g_ybuf[(size_t)NSLOT * HID];   // GEMM2 output (33 MB)

// ---------------- minimal PTX: mma + tf32 round (sm_80-era) ------------------
__device__ __forceinline__ uint32_t f2tf(float x) {
    uint32_t r; asm("cvt.rna.tf32.f32 %0, %1;" : "=r"(r) : "f"(x)); return r;
}
__device__ __forceinline__ void mma_tf32(float* c, const uint32_t* a, const uint32_t* b) {
    asm volatile(
        "mma.sync.aligned.m16n8k8.row.col.f32.tf32.tf32.f32 "
        "{%0,%1,%2,%3}, {%4,%5,%6,%7}, {%8,%9}, {%0,%1,%2,%3};"
        : "+f"(c[0]), "+f"(c[1]), "+f"(c[2]), "+f"(c[3])
        : "r"(a[0]), "r"(a[1]), "r"(a[2]), "r"(a[3]), "r"(b[0]), "r"(b[1]));
}
__device__ __forceinline__ float silu(float x) {
    return x / (1.f + __expf(-x));
}

// ---------------- kernels 0-3: routing (fp32-exact, passed in R1) -----------
__global__ void init_kernel() {
    if (threadIdx.x < NEXP) g_cnt[threadIdx.x] = 0;
}

__global__ __launch_bounds__(256) void router_kernel(
    const float* __restrict__ x, const float* __restrict__ wqkv)
{
    const int warp = threadIdx.x >> 5;
    const int lane = threadIdx.x & 31;
    const int t = blockIdx.x * 8 + warp;
    if (t >= N_TOK) return;

    const float* xr = x + (size_t)t * HID;
    float acc[24];
#pragma unroll
    for (int r = 0; r < 24; r++) acc[r] = 0.f;
    for (int j = lane; j < HID; j += 32) {
        const float xv = xr[j];
#pragma unroll
        for (int r = 0; r < 24; r++) acc[r] += xv * wqkv[r * HID + j];
    }
#pragma unroll
    for (int r = 0; r < 24; r++) {
#pragma unroll
        for (int o = 16; o > 0; o >>= 1)
            acc[r] += __shfl_down_sync(0xffffffffu, acc[r], o);
    }
    if (lane == 0) {
        float q[8], k[8], v[8], logit[8];
#pragma unroll
        for (int i = 0; i < 8; i++) { q[i]=acc[i]; k[i]=acc[8+i]; v[i]=acc[16+i]; }
#pragma unroll
        for (int e = 0; e < 8; e++) {
            float m = -1e30f;
#pragma unroll
            for (int j = 0; j < 8; j++) m = fmaxf(m, q[e]*k[j]);
            float s = 0.f, num = 0.f;
#pragma unroll
            for (int j = 0; j < 8; j++) {
                const float w = expf(q[e]*k[j] - m);
                s += w; num += w * v[j];
            }
            logit[e] = num / s;
        }
        int i1 = 0;
        for (int e = 1; e < 8; e++) if (logit[e] > logit[i1]) i1 = e;
        int i2 = -1;
        for (int e = 0; e < 8; e++) {
            if (e == i1) continue;
            if (i2 < 0 || logit[e] > logit[i2]) i2 = e;
        }
        const float e2 = expf(logit[i2] - logit[i1]);
        const float s1 = 1.f / (1.f + e2);
        const float s2 = e2 / (1.f + e2);
        g_tok_exp[t*2]   = i1;  g_tok_exp[t*2+1]   = i2;
        g_tok_score[t*2] = s1;  g_tok_score[t*2+1] = s2;
        atomicAdd(&g_cnt[i1], 1);
        atomicAdd(&g_cnt[i2], 1);
    }
}

__global__ void scan_kernel() {
    int off = 0;
    for (int e = 0; e < NEXP; e++) { g_off[e] = off; g_pos[e] = off; off += g_cnt[e]; }
    g_off[NEXP] = off;
}

__global__ void scatter_kernel() {
    const int s = blockIdx.x * blockDim.x + threadIdx.x;
    if (s >= NSLOT) return;
    const int e = g_tok_exp[s];
    const int p = atomicAdd(&g_pos[e], 1);
    g_slot_token[p] = s >> 1;
    g_slot_out[p]   = s;
    g_slot_score[p] = g_tok_score[s];
}

// ============================================================================
// GEMM1 + fused GLU (mma.sync tf32, register-prefetch double buffer)
// CTA tile: M=128 x 128 B-rows; B-rows interleave 64 'a' and paired 64 'g'
// cols in 16-row groups -> warp n8-tiles {0,1}='a', {2,3}='g' on the SAME
// output columns -> in-register GLU. BK=16, 2 stages packed in SMEM columns.
// Static SMEM: 2 x 128 x 36 floats = 36 KB. No dynamic smem, no attributes.
// ============================================================================
__global__ void __launch_bounds__(256) gemm1_mma(
    const float* __restrict__ x, const float* __restrict__ w1)
{
    __shared__ float As[128 * ROWW];
    __shared__ float Bs[128 * ROWW];

    const int e     = blockIdx.z;
    const int row0  = g_off[e];
    const int cnt   = g_off[e+1] - row0;
    const int mbase = blockIdx.y * 128;
    if (mbase >= cnt) return;
    const int n0 = blockIdx.x * 64;           // 64 'a' columns per CTA

    const int tid  = threadIdx.x;
    const int wid  = tid >> 5, lane = tid & 31;
    const int wm   = wid >> 2;                // 0..1
    const int wn   = wid & 3;                 // 0..3
    const int g    = lane >> 2;               // 0..7
    const int tg   = lane & 3;                // 0..3

    // ---- staging map: slots {tid, tid+256}; slot -> row=slot>>2, c4=slot&3
    const float* gA[2]; const float* gB[2];
    int stRow[2], stCol[2];
#pragma unroll
    for (int i = 0; i < 2; i++) {
        const int slot = tid + 256 * i;
        const int row  = slot >> 2;           // 0..127
        const int c4   = slot & 3;            // float4 within 16-col chunk
        int m = mbase + row; if (m > cnt - 1) m = cnt - 1;
        gA[i] = x + (size_t)g_slot_token[row0 + m] * HID + c4 * 4;
        const int q = row >> 4, rr = row & 15;
        const int w1row = ((q & 1) ? FF : 0) + n0 + (q >> 1) * 16 + rr;
        gB[i] = w1 + (size_t)e * FF2 * HID + (size_t)w1row * HID + c4 * 4;
        stRow[i] = row; stCol[i] = c4 * 4;
    }

    float acc[4][4][4];
#pragma unroll
    for (int mt = 0; mt < 4; mt++)
#pragma unroll
        for (int nt = 0; nt < 4; nt++)
#pragma unroll
            for (int r = 0; r < 4; r++) acc[mt][nt][r] = 0.f;

    const int NC = HID / 16;                  // 64 chunks
    float4 pa[2], pb[2];
#pragma unroll
    for (int i = 0; i < 2; i++) {             // prologue: chunk 0 -> stage 0
        pa[i] = *(const float4*)(gA[i]);
        pb[i] = *(const float4*)(gB[i]);
        *(float4*)(As + stRow[i]*ROWW + stCol[i]) = pa[i];
        *(float4*)(Bs + stRow[i]*ROWW + stCol[i]) = pb[i];
    }
    __syncthreads();

    for (int c = 0; c < NC; c++) {
        const int s = c & 1;
        const bool more = (c + 1 < NC);
        if (more) {
            const int k0 = (c + 1) * 16;
#pragma unroll
            for (int i = 0; i < 2; i++) {
                pa[i] = *(const float4*)(gA[i] + k0);
                pb[i] = *(const float4*)(gB[i] + k0);
            }
        }
        // compute on stage s (cols s*16 .. s*16+15), 2 k-steps
#pragma unroll
        for (int ks = 0; ks < 2; ks++) {
            const int cb = s * 16 + ks * 8;
            uint32_t af[4][4], bf[4][2];
#pragma unroll
            for (int mt = 0; mt < 4; mt++) {
                const int r = wm * 64 + mt * 16 + g;
                af[mt][0] = f2tf(As[ r      * ROWW + cb + tg]);
                af[mt][1] = f2tf(As[(r + 8) * ROWW + cb + tg]);
                af[mt][2] = f2tf(As[ r      * ROWW + cb + tg + 4]);
                af[mt][3] = f2tf(As[(r + 8) * ROWW + cb + tg + 4]);
            }
#pragma unroll
            for (int nt = 0; nt < 4; nt++) {
                const int br = wn * 32 + nt * 8 + g;
                bf[nt][0] = f2tf(Bs[br * ROWW + cb + tg]);
                bf[nt][1] = f2tf(Bs[br * ROWW + cb + tg + 4]);
            }
#pragma unroll
            for (int mt = 0; mt < 4; mt++)
#pragma unroll
                for (int nt = 0; nt < 4; nt++)
                    mma_tf32(acc[mt][nt], af[mt], bf[nt]);
        }
        if (more) {
            const int so = (s ^ 1) * 16;
#pragma unroll
            for (int i = 0; i < 2; i++) {
                *(float4*)(As + stRow[i]*ROWW + so + stCol[i]) = pa[i];
                *(float4*)(Bs + stRow[i]*ROWW + so + stCol[i]) = pb[i];
            }
        }
        __syncthreads();
    }

    // ---- epilogue: silu(a)*g -> g_act ----
#pragma unroll
    for (int mt = 0; mt < 4; mt++) {
        const int r0 = mbase + wm * 64 + mt * 16 + g;
        const int r1 = r0 + 8;
#pragma unroll
        for (int nt = 0; nt < 2; nt++) {
            const int col = n0 + wn * 16 + nt * 8 + tg * 2;
            const float* a0 = acc[mt][nt];
            const float* g0 = acc[mt][nt + 2];
            if (r0 < cnt) {
                float2 o = make_float2(silu(a0[0]) * g0[0], silu(a0[1]) * g0[1]);
                *(float2*)(g_act + (size_t)(row0 + r0) * FF + col) = o;
            }
            if (r1 < cnt) {
                float2 o = make_float2(silu(a0[2]) * g0[2], silu(a0[3]) * g0[3]);
                *(float2*)(g_act + (size_t)(row0 + r1) * FF + col) = o;
            }
        }
    }
}

// ============================================================================
// GEMM2 (mma.sync tf32): y[slot_out] = (act @ w2[e].T) * score
// CTA tile 128x128, BK=16, same skeleton, static 36 KB SMEM.
// ============================================================================
__global__ void __launch_bounds__(256) gemm2_mma(const float* __restrict__ w2)
{
    __shared__ float As[128 * ROWW];
    __shared__ float Bs[128 * ROWW];

    const int e     = blockIdx.z;
    const int row0  = g_off[e];
    const int cnt   = g_off[e+1] - row0;
    const int mbase = blockIdx.y * 128;
    if (mbase >= cnt) return;
    const int n0 = blockIdx.x * 128;

    const int tid = threadIdx.x;
    const int wid = tid >> 5, lane = tid & 31;
    const int wm  = wid >> 2;
    const int wn  = wid & 3;
    const int g   = lane >> 2;
    const int tg  = lane & 3;

    const float* gA[2]; const float* gB[2];
    int stRow[2], stCol[2];
#pragma unroll
    for (int i = 0; i < 2; i++) {
        const int slot = tid + 256 * i;
        const int row  = slot >> 2;
        const int c4   = slot & 3;
        int m = mbase + row; if (m > cnt - 1) m = cnt - 1;
        gA[i] = g_act + (size_t)(row0 + m) * FF + c4 * 4;
        gB[i] = w2 + (size_t)e * HID * FF + (size_t)(n0 + row) * FF + c4 * 4;
        stRow[i] = row; stCol[i] = c4 * 4;
    }

    float acc[4][4][4];
#pragma unroll
    for (int mt = 0; mt < 4; mt++)
#pragma unroll
        for (int nt = 0; nt < 4; nt++)
#pragma unroll
            for (int r = 0; r < 4; r++) acc[mt][nt][r] = 0.f;

    const int NC = FF / 16;                   // 176 chunks
    float4 pa[2], pb[2];
#pragma unroll
    for (int i = 0; i < 2; i++) {
        pa[i] = *(const float4*)(gA[i]);
        pb[i] = *(const float4*)(gB[i]);
        *(float4*)(As + stRow[i]*ROWW + stCol[i]) = pa[i];
        *(float4*)(Bs + stRow[i]*ROWW + stCol[i]) = pb[i];
    }
    __syncthreads();

    for (int c = 0; c < NC; c++) {
        const int s = c & 1;
        const bool more = (c + 1 < NC);
        if (more) {
            const int k0 = (c + 1) * 16;
#pragma unroll
            for (int i = 0; i < 2; i++) {
                pa[i] = *(const float4*)(gA[i] + k0);
                pb[i] = *(const float4*)(gB[i] + k0);
            }
        }
#pragma unroll
        for (int ks = 0; ks < 2; ks++) {
            const int cb = s * 16 + ks * 8;
            uint32_t af[4][4], bf[4][2];
#pragma unroll
            for (int mt = 0; mt < 4; mt++) {
                const int r = wm * 64 + mt * 16 + g;
                af[mt][0] = f2tf(As[ r      * ROWW + cb + tg]);
                af[mt][1] = f2tf(As[(r + 8) * ROWW + cb + tg]);
                af[mt][2] = f2tf(As[ r      * ROWW + cb + tg + 4]);
                af[mt][3] = f2tf(As[(r + 8) * ROWW + cb + tg + 4]);
            }
#pragma unroll
            for (int nt = 0; nt < 4; nt++) {
                const int br = wn * 32 + nt * 8 + g;
                bf[nt][0] = f2tf(Bs[br * ROWW + cb + tg]);
                bf[nt][1] = f2tf(Bs[br * ROWW + cb + tg + 4]);
            }
#pragma unroll
            for (int mt = 0; mt < 4; mt++)
#pragma unroll
                for (int nt = 0; nt < 4; nt++)
                    mma_tf32(acc[mt][nt], af[mt], bf[nt]);
        }
        if (more) {
            const int so = (s ^ 1) * 16;
#pragma unroll
            for (int i = 0; i < 2; i++) {
                *(float4*)(As + stRow[i]*ROWW + so + stCol[i]) = pa[i];
                *(float4*)(Bs + stRow[i]*ROWW + so + stCol[i]) = pb[i];
            }
        }
        __syncthreads();
    }

    // ---- epilogue: scale by routing score, scatter to ybuf[slot_out] ----
#pragma unroll
    for (int mt = 0; mt < 4; mt++) {
        const int r0 = mbase + wm * 64 + mt * 16 + g;
        const int r1 = r0 + 8;
        const int p0 = row0 + (r0 < cnt ? r0 : 0);
        const int p1 = row0 + (r1 < cnt ? r1 : 0);
        const float sc0 = g_slot_score[p0];
        const float sc1 = g_slot_score[p1];
        float* d0 = g_ybuf + (size_t)g_slot_out[p0] * HID;
        float* d1 = g_ybuf + (size_t)g_slot_out[p1] * HID;
#pragma unroll
        for (int nt = 0; nt < 4; nt++) {
            const int col = n0 + wn * 32 + nt * 8 + tg * 2;
            if (r0 < cnt)
                *(float2*)(d0 + col) = make_float2(sc0 * acc[mt][nt][0], sc0 * acc[mt][nt][1]);
            if (r1 < cnt)
                *(float2*)(d1 + col) = make_float2(sc1 * acc[mt][nt][2], sc1 * acc[mt][nt][3]);
        }
    }
}

// ---------------- kernel: top-k combine -------------------------------------
__global__ void combine_kernel(float* __restrict__ out) {
    const size_t total = (size_t)N_TOK * (HID/4);
    const size_t i = (size_t)blockIdx.x * blockDim.x + threadIdx.x;
    if (i >= total) return;
    const size_t t  = i / (HID/4);
    const size_t j4 = i % (HID/4);
    const float4 y0 = *((const float4*)(g_ybuf + (size_t)(2*t  ) * HID) + j4);
    const float4 y1 = *((const float4*)(g_ybuf + (size_t)(2*t+1) * HID) + j4);
    ((float4*)out)[i] = make_float4(y0.x+y1.x, y0.y+y1.y, y0.z+y1.z, y0.w+y1.w);
}

// ---------------- launch (no device-state mutation of any kind) -------------
extern "C" void kernel_launch(void* const* d_in, const int* in_sizes, int n_in,
                              void* d_out, int out_size)
{
    const float* x    = (const float*)d_in[0];
    const float* wqkv = (const float*)d_in[1];
    const float* w1   = (const float*)d_in[2];
    const float* w2   = (const float*)d_in[3];
    float* out = (float*)d_out;

    init_kernel<<<1, 32>>>();
    router_kernel<<<N_TOK/8, 256>>>(x, wqkv);
    scan_kernel<<<1, 1>>>();
    scatter_kernel<<<NSLOT/256, 256>>>();

    gemm1_mma<<<dim3(FF/64, NSLOT/128, NEXP), 256>>>(x, w1);
    gemm2_mma<<<dim3(HID/128, NSLOT/128, NEXP), 256>>>(w2);
    combine_kernel<<<(N_TOK*HID/4 + 255)/256, 256>>>(out);
}

// round 7
// speedup vs baseline: 2.8313x; 1.0444x over previous
#include <cuda_runtime.h>
#include <math.h>
#include <stdint.h>

// Problem constants (fixed shapes)
#define N_TOK 4096          // B*S
#define HID   1024
#define FF    2816
#define FF2   5632
#define NEXP  8
#define NSLOT 8192          // N_TOK * top_k

#define ROWW  36            // padded SMEM row (floats): stride 4 banks, 16B-aligned

// ---------------- scratch (static device globals) ---------------------------
static __device__ int   g_cnt[NEXP];
static __device__ int   g_off[NEXP+1];
static __device__ int   g_pos[NEXP];
static __device__ int   g_slot_token[NSLOT];
static __device__ int   g_slot_out[NSLOT];
static __device__ float g_slot_score[NSLOT];
static __device__ int   g_tok_exp[NSLOT];
static __device__ float g_tok_score[NSLOT];
static __device__ float g_act [(size_t)NSLOT * FF ];   // GLU output (92 MB)
static __device__ float g_ybuf[(size_t)NSLOT * HID];   // GEMM2 output (33 MB)

// ---------------- minimal PTX: mma + tf32 round (sm_80-era) ------------------
__device__ __forceinline__ uint32_t f2tf(float x) {
    uint32_t r; asm("cvt.rna.tf32.f32 %0, %1;" : "=r"(r) : "f"(x)); return r;
}
// convert a float4 to tf32 bit-patterns (stored back as float bits)
__device__ __forceinline__ float4 cvt4(float4 v) {
    return make_float4(__uint_as_float(f2tf(v.x)), __uint_as_float(f2tf(v.y)),
                       __uint_as_float(f2tf(v.z)), __uint_as_float(f2tf(v.w)));
}
__device__ __forceinline__ void mma_tf32(float* c, const uint32_t* a, const uint32_t* b) {
    asm volatile(
        "mma.sync.aligned.m16n8k8.row.col.f32.tf32.tf32.f32 "
        "{%0,%1,%2,%3}, {%4,%5,%6,%7}, {%8,%9}, {%0,%1,%2,%3};"
        : "+f"(c[0]), "+f"(c[1]), "+f"(c[2]), "+f"(c[3])
        : "r"(a[0]), "r"(a[1]), "r"(a[2]), "r"(a[3]), "r"(b[0]), "r"(b[1]));
}
__device__ __forceinline__ float silu(float x) {
    return x / (1.f + __expf(-x));
}

// ---------------- kernels 0-3: routing (fp32-exact, proven) -----------------
__global__ void init_kernel() {
    if (threadIdx.x < NEXP) g_cnt[threadIdx.x] = 0;
}

__global__ __launch_bounds__(256) void router_kernel(
    const float* __restrict__ x, const float* __restrict__ wqkv)
{
    const int warp = threadIdx.x >> 5;
    const int lane = threadIdx.x & 31;
    const int t = blockIdx.x * 8 + warp;
    if (t >= N_TOK) return;

    const float* xr = x + (size_t)t * HID;
    float acc[24];
#pragma unroll
    for (int r = 0; r < 24; r++) acc[r] = 0.f;
    for (int j = lane; j < HID; j += 32) {
        const float xv = xr[j];
#pragma unroll
        for (int r = 0; r < 24; r++) acc[r] += xv * wqkv[r * HID + j];
    }
#pragma unroll
    for (int r = 0; r < 24; r++) {
#pragma unroll
        for (int o = 16; o > 0; o >>= 1)
            acc[r] += __shfl_down_sync(0xffffffffu, acc[r], o);
    }
    if (lane == 0) {
        float q[8], k[8], v[8], logit[8];
#pragma unroll
        for (int i = 0; i < 8; i++) { q[i]=acc[i]; k[i]=acc[8+i]; v[i]=acc[16+i]; }
#pragma unroll
        for (int e = 0; e < 8; e++) {
            float m = -1e30f;
#pragma unroll
            for (int j = 0; j < 8; j++) m = fmaxf(m, q[e]*k[j]);
            float s = 0.f, num = 0.f;
#pragma unroll
            for (int j = 0; j < 8; j++) {
                const float w = expf(q[e]*k[j] - m);
                s += w; num += w * v[j];
            }
            logit[e] = num / s;
        }
        int i1 = 0;
        for (int e = 1; e < 8; e++) if (logit[e] > logit[i1]) i1 = e;
        int i2 = -1;
        for (int e = 0; e < 8; e++) {
            if (e == i1) continue;
            if (i2 < 0 || logit[e] > logit[i2]) i2 = e;
        }
        const float e2 = expf(logit[i2] - logit[i1]);
        const float s1 = 1.f / (1.f + e2);
        const float s2 = e2 / (1.f + e2);
        g_tok_exp[t*2]   = i1;  g_tok_exp[t*2+1]   = i2;
        g_tok_score[t*2] = s1;  g_tok_score[t*2+1] = s2;
        atomicAdd(&g_cnt[i1], 1);
        atomicAdd(&g_cnt[i2], 1);
    }
}

__global__ void scan_kernel() {
    int off = 0;
    for (int e = 0; e < NEXP; e++) { g_off[e] = off; g_pos[e] = off; off += g_cnt[e]; }
    g_off[NEXP] = off;
}

__global__ void scatter_kernel() {
    const int s = blockIdx.x * blockDim.x + threadIdx.x;
    if (s >= NSLOT) return;
    const int e = g_tok_exp[s];
    const int p = atomicAdd(&g_pos[e], 1);
    g_slot_token[p] = s >> 1;
    g_slot_out[p]   = s;
    g_slot_score[p] = g_tok_score[s];
}

// ============================================================================
// GEMM1 + fused GLU (mma.sync tf32, register-prefetch double buffer)
// SMEM holds PRE-CONVERTED tf32 bit patterns: cvt happens once at staging
// (16 cvt/chunk/thread) instead of on every fragment load (was 96) -> the
// inner loop is pure LDS + MMA.
// CTA tile: M=128 x 128 B-rows (interleaved 'a'/'g' 16-row groups -> warp
// n8-tiles {0,1}='a', {2,3}='g' on identical output columns -> in-register
// GLU). BK=16, 2 stages packed in SMEM columns. Static SMEM 36 KB.
// ============================================================================
__global__ void __launch_bounds__(256) gemm1_mma(
    const float* __restrict__ x, const float* __restrict__ w1)
{
    __shared__ float As[128 * ROWW];
    __shared__ float Bs[128 * ROWW];

    const int e     = blockIdx.z;
    const int row0  = g_off[e];
    const int cnt   = g_off[e+1] - row0;
    const int mbase = blockIdx.y * 128;
    if (mbase >= cnt) return;
    const int n0 = blockIdx.x * 64;           // 64 'a' columns per CTA

    const int tid  = threadIdx.x;
    const int wid  = tid >> 5, lane = tid & 31;
    const int wm   = wid >> 2;                // 0..1
    const int wn   = wid & 3;                 // 0..3
    const int g    = lane >> 2;               // 0..7
    const int tg   = lane & 3;                // 0..3

    // ---- staging map: slots {tid, tid+256}; slot -> row=slot>>2, c4=slot&3
    const float* gA[2]; const float* gB[2];
    int stRow[2], stCol[2];
#pragma unroll
    for (int i = 0; i < 2; i++) {
        const int slot = tid + 256 * i;
        const int row  = slot >> 2;           // 0..127
        const int c4   = slot & 3;            // float4 within 16-col chunk
        int m = mbase + row; if (m > cnt - 1) m = cnt - 1;
        gA[i] = x + (size_t)g_slot_token[row0 + m] * HID + c4 * 4;
        const int q = row >> 4, rr = row & 15;
        const int w1row = ((q & 1) ? FF : 0) + n0 + (q >> 1) * 16 + rr;
        gB[i] = w1 + (size_t)e * FF2 * HID + (size_t)w1row * HID + c4 * 4;
        stRow[i] = row; stCol[i] = c4 * 4;
    }

    float acc[4][4][4];
#pragma unroll
    for (int mt = 0; mt < 4; mt++)
#pragma unroll
        for (int nt = 0; nt < 4; nt++)
#pragma unroll
            for (int r = 0; r < 4; r++) acc[mt][nt][r] = 0.f;

    const int NC = HID / 16;                  // 64 chunks
    float4 pa[2], pb[2];
#pragma unroll
    for (int i = 0; i < 2; i++) {             // prologue: chunk 0 -> stage 0
        pa[i] = *(const float4*)(gA[i]);
        pb[i] = *(const float4*)(gB[i]);
        *(float4*)(As + stRow[i]*ROWW + stCol[i]) = cvt4(pa[i]);
        *(float4*)(Bs + stRow[i]*ROWW + stCol[i]) = cvt4(pb[i]);
    }
    __syncthreads();

    for (int c = 0; c < NC; c++) {
        const int s = c & 1;
        const bool more = (c + 1 < NC);
        if (more) {
            const int k0 = (c + 1) * 16;
#pragma unroll
            for (int i = 0; i < 2; i++) {
                pa[i] = *(const float4*)(gA[i] + k0);
                pb[i] = *(const float4*)(gB[i] + k0);
            }
        }
        // compute on stage s (cols s*16 .. s*16+15), 2 k-steps; SMEM holds
        // tf32 bits -> plain LDS, no cvt in the hot loop.
#pragma unroll
        for (int ks = 0; ks < 2; ks++) {
            const int cb = s * 16 + ks * 8;
            uint32_t af[4][4], bf[4][2];
#pragma unroll
            for (int mt = 0; mt < 4; mt++) {
                const int r = wm * 64 + mt * 16 + g;
                af[mt][0] = __float_as_uint(As[ r      * ROWW + cb + tg]);
                af[mt][1] = __float_as_uint(As[(r + 8) * ROWW + cb + tg]);
                af[mt][2] = __float_as_uint(As[ r      * ROWW + cb + tg + 4]);
                af[mt][3] = __float_as_uint(As[(r + 8) * ROWW + cb + tg + 4]);
            }
#pragma unroll
            for (int nt = 0; nt < 4; nt++) {
                const int br = wn * 32 + nt * 8 + g;
                bf[nt][0] = __float_as_uint(Bs[br * ROWW + cb + tg]);
                bf[nt][1] = __float_as_uint(Bs[br * ROWW + cb + tg + 4]);
            }
#pragma unroll
            for (int mt = 0; mt < 4; mt++)
#pragma unroll
                for (int nt = 0; nt < 4; nt++)
                    mma_tf32(acc[mt][nt], af[mt], bf[nt]);
        }
        if (more) {
            const int so = (s ^ 1) * 16;
#pragma unroll
            for (int i = 0; i < 2; i++) {
                *(float4*)(As + stRow[i]*ROWW + so + stCol[i]) = cvt4(pa[i]);
                *(float4*)(Bs + stRow[i]*ROWW + so + stCol[i]) = cvt4(pb[i]);
            }
        }
        __syncthreads();
    }

    // ---- epilogue: silu(a)*g -> g_act ----
#pragma unroll
    for (int mt = 0; mt < 4; mt++) {
        const int r0 = mbase + wm * 64 + mt * 16 + g;
        const int r1 = r0 + 8;
#pragma unroll
        for (int nt = 0; nt < 2; nt++) {
            const int col = n0 + wn * 16 + nt * 8 + tg * 2;
            const float* a0 = acc[mt][nt];
            const float* g0 = acc[mt][nt + 2];
            if (r0 < cnt) {
                float2 o = make_float2(silu(a0[0]) * g0[0], silu(a0[1]) * g0[1]);
                *(float2*)(g_act + (size_t)(row0 + r0) * FF + col) = o;
            }
            if (r1 < cnt) {
                float2 o = make_float2(silu(a0[2]) * g0[2], silu(a0[3]) * g0[3]);
                *(float2*)(g_act + (size_t)(row0 + r1) * FF + col) = o;
            }
        }
    }
}

// ============================================================================
// GEMM2 (mma.sync tf32): y[slot_out] = (act @ w2[e].T) * score
// CTA tile 128x128, BK=16, same pre-converted-staging skeleton.
// ============================================================================
__global__ void __launch_bounds__(256) gemm2_mma(const float* __restrict__ w2)
{
    __shared__ float As[128 * ROWW];
    __shared__ float Bs[128 * ROWW];

    const int e     = blockIdx.z;
    const int row0  = g_off[e];
    const int cnt   = g_off[e+1] - row0;
    const int mbase = blockIdx.y * 128;
    if (mbase >= cnt) return;
    const int n0 = blockIdx.x * 128;

    const int tid = threadIdx.x;
    const int wid = tid >> 5, lane = tid & 31;
    const int wm  = wid >> 2;
    const int wn  = wid & 3;
    const int g   = lane >> 2;
    const int tg  = lane & 3;

    const float* gA[2]; const float* gB[2];
    int stRow[2], stCol[2];
#pragma unroll
    for (int i = 0; i < 2; i++) {
        const int slot = tid + 256 * i;
        const int row  = slot >> 2;
        const int c4   = slot & 3;
        int m = mbase + row; if (m > cnt - 1) m = cnt - 1;
        gA[i] = g_act + (size_t)(row0 + m) * FF + c4 * 4;
        gB[i] = w2 + (size_t)e * HID * FF + (size_t)(n0 + row) * FF + c4 * 4;
        stRow[i] = row; stCol[i] = c4 * 4;
    }

    float acc[4][4][4];
#pragma unroll
    for (int mt = 0; mt < 4; mt++)
#pragma unroll
        for (int nt = 0; nt < 4; nt++)
#pragma unroll
            for (int r = 0; r < 4; r++) acc[mt][nt][r] = 0.f;

    const int NC = FF / 16;                   // 176 chunks
    float4 pa[2], pb[2];
#pragma unroll
    for (int i = 0; i < 2; i++) {
        pa[i] = *(const float4*)(gA[i]);
        pb[i] = *(const float4*)(gB[i]);
        *(float4*)(As + stRow[i]*ROWW + stCol[i]) = cvt4(pa[i]);
        *(float4*)(Bs + stRow[i]*ROWW + stCol[i]) = cvt4(pb[i]);
    }
    __syncthreads();

    for (int c = 0; c < NC; c++) {
        const int s = c & 1;
        const bool more = (c + 1 < NC);
        if (more) {
            const int k0 = (c + 1) * 16;
#pragma unroll
            for (int i = 0; i < 2; i++) {
                pa[i] = *(const float4*)(gA[i] + k0);
                pb[i] = *(const float4*)(gB[i] + k0);
            }
        }
#pragma unroll
        for (int ks = 0; ks < 2; ks++) {
            const int cb = s * 16 + ks * 8;
            uint32_t af[4][4], bf[4][2];
#pragma unroll
            for (int mt = 0; mt < 4; mt++) {
                const int r = wm * 64 + mt * 16 + g;
                af[mt][0] = __float_as_uint(As[ r      * ROWW + cb + tg]);
                af[mt][1] = __float_as_uint(As[(r + 8) * ROWW + cb + tg]);
                af[mt][2] = __float_as_uint(As[ r      * ROWW + cb + tg + 4]);
                af[mt][3] = __float_as_uint(As[(r + 8) * ROWW + cb + tg + 4]);
            }
#pragma unroll
            for (int nt = 0; nt < 4; nt++) {
                const int br = wn * 32 + nt * 8 + g;
                bf[nt][0] = __float_as_uint(Bs[br * ROWW + cb + tg]);
                bf[nt][1] = __float_as_uint(Bs[br * ROWW + cb + tg + 4]);
            }
#pragma unroll
            for (int mt = 0; mt < 4; mt++)
#pragma unroll
                for (int nt = 0; nt < 4; nt++)
                    mma_tf32(acc[mt][nt], af[mt], bf[nt]);
        }
        if (more) {
            const int so = (s ^ 1) * 16;
#pragma unroll
            for (int i = 0; i < 2; i++) {
                *(float4*)(As + stRow[i]*ROWW + so + stCol[i]) = cvt4(pa[i]);
                *(float4*)(Bs + stRow[i]*ROWW + so + stCol[i]) = cvt4(pb[i]);
            }
        }
        __syncthreads();
    }

    // ---- epilogue: scale by routing score, scatter to ybuf[slot_out] ----
#pragma unroll
    for (int mt = 0; mt < 4; mt++) {
        const int r0 = mbase + wm * 64 + mt * 16 + g;
        const int r1 = r0 + 8;
        const int p0 = row0 + (r0 < cnt ? r0 : 0);
        const int p1 = row0 + (r1 < cnt ? r1 : 0);
        const float sc0 = g_slot_score[p0];
        const float sc1 = g_slot_score[p1];
        float* d0 = g_ybuf + (size_t)g_slot_out[p0] * HID;
        float* d1 = g_ybuf + (size_t)g_slot_out[p1] * HID;
#pragma unroll
        for (int nt = 0; nt < 4; nt++) {
            const int col = n0 + wn * 32 + nt * 8 + tg * 2;
            if (r0 < cnt)
                *(float2*)(d0 + col) = make_float2(sc0 * acc[mt][nt][0], sc0 * acc[mt][nt][1]);
            if (r1 < cnt)
                *(float2*)(d1 + col) = make_float2(sc1 * acc[mt][nt][2], sc1 * acc[mt][nt][3]);
        }
    }
}

// ---------------- kernel: top-k combine -------------------------------------
__global__ void combine_kernel(float* __restrict__ out) {
    const size_t total = (size_t)N_TOK * (HID/4);
    const size_t i = (size_t)blockIdx.x * blockDim.x + threadIdx.x;
    if (i >= total) return;
    const size_t t  = i / (HID/4);
    const size_t j4 = i % (HID/4);
    const float4 y0 = *((const float4*)(g_ybuf + (size_t)(2*t  ) * HID) + j4);
    const float4 y1 = *((const float4*)(g_ybuf + (size_t)(2*t+1) * HID) + j4);
    ((float4*)out)[i] = make_float4(y0.x+y1.x, y0.y+y1.y, y0.z+y1.z, y0.w+y1.w);
}

// ---------------- launch (no device-state mutation of any kind) -------------
extern "C" void kernel_launch(void* const* d_in, const int* in_sizes, int n_in,
                              void* d_out, int out_size)
{
    const float* x    = (const float*)d_in[0];
    const float* wqkv = (const float*)d_in[1];
    const float* w1   = (const float*)d_in[2];
    const float* w2   = (const float*)d_in[3];
    float* out = (float*)d_out;

    init_kernel<<<1, 32>>>();
    router_kernel<<<N_TOK/8, 256>>>(x, wqkv);
    scan_kernel<<<1, 1>>>();
    scatter_kernel<<<NSLOT/256, 256>>>();

    gemm1_mma<<<dim3(FF/64, NSLOT/128, NEXP), 256>>>(x, w1);
    gemm2_mma<<<dim3(HID/128, NSLOT/128, NEXP), 256>>>(w2);
    combine_kernel<<<(N_TOK*HID/4 + 255)/256, 256>>>(out);
}